// round 14
// baseline (speedup 1.0000x reference)
#include <cuda_runtime.h>

#define N_NODES 50000
#define N_EDGES 600000
#define DIM 128
#define N_LAYERS 3
#define N_GRAPHS 512
#define BN_EPS 1e-5f
#define OUT_ELEMS (N_GRAPHS * N_LAYERS * DIM)

#define MROWS 128        // rows per mlp block
#define AST 130          // As / H1 smem row stride (floats): 8*130 % 32 = 16 -> conflict-free

// Scratch (device globals; no allocation allowed)
__device__ float g_agg[N_NODES * DIM];            // aggregation output (mlp input)
__device__ float g_h2[N_NODES * DIM];             // raw mlp output (pre-BN)
__device__ float g_stats[N_LAYERS][2 * DIM];      // per-layer per-feature sum, sumsq
// CSR build scratch
__device__ int g_deg[N_NODES];
__device__ int g_cur[N_NODES];
__device__ int g_off[N_NODES];
__device__ int g_esrc[N_EDGES];

// ---------------------------------------------------------------------------
__device__ __forceinline__ void red_add_v4(float4* p, float4 v) {
    asm volatile("red.global.add.v4.f32 [%0], {%1, %2, %3, %4};\n"
                 :: "l"(p), "f"(v.x), "f"(v.y), "f"(v.z), "f"(v.w)
                 : "memory");
}
__device__ __forceinline__ void fma2(unsigned long long& d,
                                     unsigned long long a, unsigned long long b) {
    asm("fma.rn.f32x2 %0, %1, %2, %0;" : "+l"(d) : "l"(a), "l"(b));
}
__device__ __forceinline__ unsigned long long pack2(float x) {
    unsigned long long r;
    asm("mov.b64 %0, {%1, %1};" : "=l"(r) : "f"(x));
    return r;
}
__device__ __forceinline__ float2 unpack2(unsigned long long v) {
    float2 f;
    asm("mov.b64 {%0, %1}, %2;" : "=f"(f.x), "=f"(f.y) : "l"(v));
    return f;
}

// BN scale/shift for a feature f from stats of layer `l`
__device__ __forceinline__ void bn_coeffs(int l, int f,
                                          const float* __restrict__ gamma,
                                          const float* __restrict__ beta,
                                          float& sc, float& sh) {
    const float* st = g_stats[l];
    float n = (float)N_NODES;
    float mean = st[f] / n;
    float var = st[DIM + f] / n - mean * mean;
    var = fmaxf(var, 0.f);
    sc = rsqrtf(var + BN_EPS) * __ldg(gamma + f);
    sh = fmaf(-mean, sc, __ldg(beta + f));
}

// ===========================================================================
// K_prep: zero deg/cur, all per-layer BN stats, and the output buffer
// ===========================================================================
__global__ void k_prep(float* __restrict__ out) {
    int i = blockIdx.x * blockDim.x + threadIdx.x;
    if (i < OUT_ELEMS) out[i] = 0.0f;
    if (i < N_NODES) { g_deg[i] = 0; g_cur[i] = 0; }
    if (i < N_LAYERS * 2 * DIM) ((float*)g_stats)[i] = 0.0f;
}

__global__ void k_hist(const int* __restrict__ dst) {
    int e = blockIdx.x * blockDim.x + threadIdx.x;
    if (e < N_EDGES) atomicAdd(&g_deg[__ldg(dst + e)], 1);
}

// single-block exclusive scan of g_deg -> g_off
#define SCAN_T 1024
#define SCAN_CH 49
__global__ __launch_bounds__(SCAN_T)
void k_scan() {
    __shared__ int s[SCAN_T];
    int t = threadIdx.x;
    int start = t * SCAN_CH;
    int end = min(start + SCAN_CH, N_NODES);
    int sum = 0;
    for (int i = start; i < end; i++) sum += g_deg[i];
    s[t] = sum;
    __syncthreads();
    #pragma unroll
    for (int d = 1; d < SCAN_T; d <<= 1) {
        int x = (t >= d) ? s[t - d] : 0;
        __syncthreads();
        s[t] += x;
        __syncthreads();
    }
    int run = (t > 0) ? s[t - 1] : 0;
    for (int i = start; i < end; i++) {
        g_off[i] = run;
        run += g_deg[i];
    }
}

__global__ void k_place(const int* __restrict__ src, const int* __restrict__ dst) {
    int e = blockIdx.x * blockDim.x + threadIdx.x;
    if (e >= N_EDGES) return;
    int d = __ldg(dst + e);
    int pos = g_off[d] + atomicAdd(&g_cur[d], 1);
    g_esrc[pos] = __ldg(src + e);
}

// ===========================================================================
// K_agg: agg[n] = BN_fold( raw[n] + sum raw[src] )
//   layer 0 (use_x): source is x, no fold.
//   layer >0: source is g_h2 (raw), fold: agg = sc*sum + (deg+1)*sh.
//   warp per node, lane per float4, 4-edge unroll. No atomics.
// ===========================================================================
__global__ void k_agg(const float4* __restrict__ x, int use_x,
                      const float* __restrict__ gamma, const float* __restrict__ beta,
                      int prev_layer) {
    __shared__ float s_st[2 * DIM];
    if (!use_x && threadIdx.x < DIM) {
        float sc, sh;
        bn_coeffs(prev_layer, threadIdx.x, gamma, beta, sc, sh);
        s_st[threadIdx.x] = sc;
        s_st[DIM + threadIdx.x] = sh;
    }
    if (!use_x) __syncthreads();

    int gt = blockIdx.x * blockDim.x + threadIdx.x;
    int node = gt >> 5;
    int lane = gt & 31;
    if (node >= N_NODES) return;
    const float4* hin = use_x ? x : (const float4*)g_h2;

    float4 acc = __ldg(hin + node * 32 + lane);   // self term (eps=0)
    int deg = __ldg(g_deg + node);
    int e   = __ldg(g_off + node);
    int end = e + deg;

    for (; e + 3 < end; e += 4) {
        int s0 = __ldg(g_esrc + e);
        int s1 = __ldg(g_esrc + e + 1);
        int s2 = __ldg(g_esrc + e + 2);
        int s3 = __ldg(g_esrc + e + 3);
        float4 v0 = __ldg(hin + s0 * 32 + lane);
        float4 v1 = __ldg(hin + s1 * 32 + lane);
        float4 v2 = __ldg(hin + s2 * 32 + lane);
        float4 v3 = __ldg(hin + s3 * 32 + lane);
        acc.x += v0.x + v1.x + v2.x + v3.x;
        acc.y += v0.y + v1.y + v2.y + v3.y;
        acc.z += v0.z + v1.z + v2.z + v3.z;
        acc.w += v0.w + v1.w + v2.w + v3.w;
    }
    for (; e < end; e++) {
        int s0 = __ldg(g_esrc + e);
        float4 v0 = __ldg(hin + s0 * 32 + lane);
        acc.x += v0.x; acc.y += v0.y; acc.z += v0.z; acc.w += v0.w;
    }

    if (!use_x) {
        float4 s = ((const float4*)s_st)[lane];
        float4 t = ((const float4*)s_st)[32 + lane];
        float k1 = (float)(deg + 1);
        acc.x = fmaf(acc.x, s.x, k1 * t.x);
        acc.y = fmaf(acc.y, s.y, k1 * t.y);
        acc.z = fmaf(acc.z, s.z, k1 * t.z);
        acc.w = fmaf(acc.w, s.w, k1 * t.w);
    }
    ((float4*)g_agg)[node * 32 + lane] = acc;
}

// ===========================================================================
// K_mlp: 128-row block, 8x8 thread tile, 256 threads, f32x2 FMA.
//   h2raw = relu(relu(agg@W1+b1)@W2+b2) -> g_h2 (separate buffer),
//   BN stats (sum,sumsq) -> g_stats[layer].
// ===========================================================================
__global__ __launch_bounds__(256, 1)
void k_mlp(const float4* __restrict__ W1, const float* __restrict__ b1,
           const float4* __restrict__ W2, const float* __restrict__ b2,
           int layer) {
    extern __shared__ float sm[];
    float*  As = sm;                      // [128][AST]
    float*  Ws = sm + MROWS * AST;        // [128][128] k-major
    float*  H1 = Ws + DIM * DIM;          // [128][AST]
    float4* Ws4 = (float4*)Ws;

    const int tid  = threadIdx.x;
    const int base = blockIdx.x * MROWS;

    // load W1 (4096 float4)
    #pragma unroll
    for (int i = 0; i < 16; i++) Ws4[tid + i * 256] = W1[tid + i * 256];
    // load A tile with row stride AST (float2 stores keep 8B alignment)
    const float4* A4 = (const float4*)g_agg;
    #pragma unroll
    for (int i = 0; i < 16; i++) {
        int idx = tid + i * 256;
        int r = idx >> 5, kq = idx & 31;
        float4 v = make_float4(0.f, 0.f, 0.f, 0.f);
        if (base + r < N_NODES) v = A4[(base + r) * 32 + kq];
        float2* p2 = (float2*)(As + r * AST + kq * 4);
        p2[0] = make_float2(v.x, v.y);
        p2[1] = make_float2(v.z, v.w);
    }
    __syncthreads();

    const int colg = tid & 15;
    const int rowg = tid >> 4;
    const int r0 = rowg * 8;
    const int cb0 = colg * 4;          // first col group
    const int cb1 = 64 + colg * 4;     // second col group

    // ---- GEMM 1: acc = A @ W1 ----
    unsigned long long acc[8][4];
    #pragma unroll
    for (int i = 0; i < 8; i++)
        #pragma unroll
        for (int p = 0; p < 4; p++) acc[i][p] = 0ull;

    #pragma unroll 2
    for (int k = 0; k < DIM; k++) {
        unsigned long long a[8];
        #pragma unroll
        for (int i = 0; i < 8; i++) a[i] = pack2(As[(r0 + i) * AST + k]);
        ulonglong2 q0 = *(const ulonglong2*)(Ws + k * DIM + cb0);
        ulonglong2 q1 = *(const ulonglong2*)(Ws + k * DIM + cb1);
        #pragma unroll
        for (int i = 0; i < 8; i++) {
            fma2(acc[i][0], a[i], q0.x);
            fma2(acc[i][1], a[i], q0.y);
            fma2(acc[i][2], a[i], q1.x);
            fma2(acc[i][3], a[i], q1.y);
        }
    }

    // epilogue 1: relu(+b1) -> H1 (row-major, stride AST)
    #pragma unroll
    for (int p = 0; p < 4; p++) {
        int colp = (p < 2) ? (cb0 + 2 * p) : (cb1 + 2 * (p - 2));
        float b_lo = __ldg(b1 + colp);
        float b_hi = __ldg(b1 + colp + 1);
        #pragma unroll
        for (int i = 0; i < 8; i++) {
            float2 f = unpack2(acc[i][p]);
            H1[(r0 + i) * AST + colp]     = fmaxf(f.x + b_lo, 0.f);
            H1[(r0 + i) * AST + colp + 1] = fmaxf(f.y + b_hi, 0.f);
        }
    }
    __syncthreads();

    // load W2 over Ws; zero smem stat buffer (As region now idle)
    #pragma unroll
    for (int i = 0; i < 16; i++) Ws4[tid + i * 256] = W2[tid + i * 256];
    As[tid] = 0.f;   // 256 slots: [0..127]=sum, [128..255]=sumsq
    __syncthreads();

    // ---- GEMM 2: acc = H1 @ W2 ----
    #pragma unroll
    for (int i = 0; i < 8; i++)
        #pragma unroll
        for (int p = 0; p < 4; p++) acc[i][p] = 0ull;

    #pragma unroll 2
    for (int k = 0; k < DIM; k++) {
        unsigned long long a[8];
        #pragma unroll
        for (int i = 0; i < 8; i++) a[i] = pack2(H1[(r0 + i) * AST + k]);
        ulonglong2 q0 = *(const ulonglong2*)(Ws + k * DIM + cb0);
        ulonglong2 q1 = *(const ulonglong2*)(Ws + k * DIM + cb1);
        #pragma unroll
        for (int i = 0; i < 8; i++) {
            fma2(acc[i][0], a[i], q0.x);
            fma2(acc[i][1], a[i], q0.y);
            fma2(acc[i][2], a[i], q1.x);
            fma2(acc[i][3], a[i], q1.y);
        }
    }

    // epilogue 2: relu(+b2) -> v, store raw h2 to g_h2, BN stats
    float v[8][8];   // [row][jj]: jj 0..3 -> cols cb0..+3, jj 4..7 -> cb1..+3
    #pragma unroll
    for (int p = 0; p < 4; p++) {
        int colp = (p < 2) ? (cb0 + 2 * p) : (cb1 + 2 * (p - 2));
        int jj = 2 * p;
        float b_lo = __ldg(b2 + colp);
        float b_hi = __ldg(b2 + colp + 1);
        #pragma unroll
        for (int i = 0; i < 8; i++) {
            float2 f = unpack2(acc[i][p]);
            v[i][jj]     = fmaxf(f.x + b_lo, 0.f);
            v[i][jj + 1] = fmaxf(f.y + b_hi, 0.f);
        }
    }

    float4* O4 = (float4*)g_h2;
    #pragma unroll
    for (int i = 0; i < 8; i++) {
        int row = base + r0 + i;
        if (row < N_NODES) {
            O4[row * 32 + colg]      = make_float4(v[i][0], v[i][1], v[i][2], v[i][3]);
            O4[row * 32 + 16 + colg] = make_float4(v[i][4], v[i][5], v[i][6], v[i][7]);
        }
    }

    #pragma unroll
    for (int jj = 0; jj < 8; jj++) {
        int col = (jj < 4) ? (cb0 + jj) : (cb1 + jj - 4);
        float s = 0.f, q = 0.f;
        #pragma unroll
        for (int i = 0; i < 8; i++) {
            if (base + r0 + i < N_NODES) { s += v[i][jj]; q += v[i][jj] * v[i][jj]; }
        }
        atomicAdd(&As[col], s);
        atomicAdd(&As[DIM + col], q);
    }
    __syncthreads();
    atomicAdd(&g_stats[layer][tid & 255], As[tid]);   // one slot per thread
}

// ===========================================================================
// K_pool: y = BN(h2raw) in registers, red into out. No h write.
// ===========================================================================
__global__ void k_pool(const int* __restrict__ batch, float* __restrict__ out,
                       const float* __restrict__ gamma, const float* __restrict__ beta,
                       int layer) {
    __shared__ float s_st[2 * DIM];
    if (threadIdx.x < DIM) {
        float sc, sh;
        bn_coeffs(layer, threadIdx.x, gamma, beta, sc, sh);
        s_st[threadIdx.x] = sc;
        s_st[DIM + threadIdx.x] = sh;
    }
    __syncthreads();

    int idx = blockIdx.x * blockDim.x + threadIdx.x;  // 1.6M exact
    int row = idx >> 5, cq = idx & 31;
    float4 xv = ((const float4*)g_h2)[idx];
    float4 s = ((const float4*)s_st)[cq];
    float4 t = ((const float4*)s_st)[32 + cq];
    float4 y;
    y.x = fmaf(xv.x, s.x, t.x);
    y.y = fmaf(xv.y, s.y, t.y);
    y.z = fmaf(xv.z, s.z, t.z);
    y.w = fmaf(xv.w, s.w, t.w);
    int g = __ldg(batch + row);
    red_add_v4((float4*)(out + g * (N_LAYERS * DIM) + layer * DIM + (cq << 2)), y);
}

// ---------------------------------------------------------------------------
extern "C" void kernel_launch(void* const* d_in, const int* in_sizes, int n_in,
                              void* d_out, int out_size) {
    const float* x      = (const float*)d_in[0];
    const int*   ei     = (const int*)d_in[1];
    const int*   batch  = (const int*)d_in[2];
    const float* W1s    = (const float*)d_in[3];
    const float* b1s    = (const float*)d_in[4];
    const float* W2s    = (const float*)d_in[5];
    const float* b2s    = (const float*)d_in[6];
    const float* gammas = (const float*)d_in[7];
    const float* betas  = (const float*)d_in[8];
    float* out = (float*)d_out;

    const int smem_mlp = (MROWS * AST + DIM * DIM + MROWS * AST) * 4;  // 198656 B
    cudaFuncSetAttribute(k_mlp, cudaFuncAttributeMaxDynamicSharedMemorySize, smem_mlp);

    const int* src = ei;
    const int* dst = ei + N_EDGES;

    const int node_blocks = (N_NODES * 32) / 256;                 // 6250
    const int edge_blocks = (N_EDGES + 255) / 256;                // 2344
    const int prep_blocks = (OUT_ELEMS + 255) / 256;              // 768
    const int mlp_blocks  = (N_NODES + MROWS - 1) / MROWS;        // 391

    k_prep<<<prep_blocks, 256>>>(out);
    k_hist<<<edge_blocks, 256>>>(dst);
    k_scan<<<1, SCAN_T>>>();
    k_place<<<edge_blocks, 256>>>(src, dst);

    for (int l = 0; l < N_LAYERS; l++) {
        int use_x = (l == 0) ? 1 : 0;
        // gamma/beta of PREVIOUS layer for the agg BN-fold (unused when l==0)
        const float* g_prev = gammas + (l > 0 ? (l - 1) : 0) * DIM;
        const float* b_prev = betas  + (l > 0 ? (l - 1) : 0) * DIM;
        k_agg<<<node_blocks, 256>>>((const float4*)x, use_x, g_prev, b_prev, l - 1);
        k_mlp<<<mlp_blocks, 256, smem_mlp>>>(
            (const float4*)(W1s + l * DIM * DIM), b1s + l * DIM,
            (const float4*)(W2s + l * DIM * DIM), b2s + l * DIM, l);
        k_pool<<<node_blocks, 256>>>(batch, out, gammas + l * DIM, betas + l * DIM, l);
    }
}

// round 17
// speedup vs baseline: 1.1635x; 1.1635x over previous
#include <cuda_runtime.h>
#include <cuda_bf16.h>
#include <cstdint>

#define N_NODES 50000
#define N_EDGES 600000
#define DIM 128
#define N_LAYERS 3
#define N_GRAPHS 512
#define BN_EPS 1e-5f
#define OUT_ELEMS (N_GRAPHS * N_LAYERS * DIM)

#define MROWS 128        // rows per mlp block

// Scratch (device globals; no allocation allowed)
__device__ float g_agg[N_NODES * DIM];    // agg / h2 buffer (in-place reuse)
__device__ float g_h[N_NODES * DIM];      // h after BN
__device__ float g_stats[2 * DIM];        // per-feature sum, sumsq
// CSR build scratch
__device__ int g_deg[N_NODES];
__device__ int g_cur[N_NODES];
__device__ int g_off[N_NODES];
__device__ int g_esrc[N_EDGES];

// ---------------------------------------------------------------------------
__device__ __forceinline__ void red_add_v4(float4* p, float4 v) {
    asm volatile("red.global.add.v4.f32 [%0], {%1, %2, %3, %4};\n"
                 :: "l"(p), "f"(v.x), "f"(v.y), "f"(v.z), "f"(v.w)
                 : "memory");
}

// m16n8k16 row.col bf16 MMA, fp32 accum (base PTX, sm_80+ — no arch feature)
__device__ __forceinline__ void mma16816(float* d, const uint32_t* a,
                                         uint32_t b0, uint32_t b1) {
    asm volatile(
        "mma.sync.aligned.m16n8k16.row.col.f32.bf16.bf16.f32 "
        "{%0,%1,%2,%3}, {%4,%5,%6,%7}, {%8,%9}, {%0,%1,%2,%3};"
        : "+f"(d[0]), "+f"(d[1]), "+f"(d[2]), "+f"(d[3])
        : "r"(a[0]), "r"(a[1]), "r"(a[2]), "r"(a[3]), "r"(b0), "r"(b1));
}

__device__ __forceinline__ void bsplit(float f, unsigned short& h, unsigned short& l) {
    __nv_bfloat16 bh = __float2bfloat16(f);
    float r = f - __bfloat162float(bh);
    __nv_bfloat16 bl = __float2bfloat16(r);
    h = *(unsigned short*)&bh;
    l = *(unsigned short*)&bl;
}
__device__ __forceinline__ uint32_t pk(unsigned short a, unsigned short b) {
    return (uint32_t)a | ((uint32_t)b << 16);
}

// smem halves-stride: 136 halves/row (68 words): bank = 4g+tig+8ks -> conflict-free
#define HST 136
#define WST 68
// smem byte offsets
#define S_AH   0
#define S_AL   34816
#define S_W1H  69632
#define S_W1L  104448
#define S_W2H  139264
#define S_W2L  174080
#define S_STAT 208896
#define S_TOTAL (208896 + 1024)

// ===========================================================================
// CSR build + prep (round-13 winner, verbatim)
// ===========================================================================
__global__ void k_prep(float* __restrict__ out) {
    int i = blockIdx.x * blockDim.x + threadIdx.x;
    if (i < OUT_ELEMS) out[i] = 0.0f;
    if (i < N_NODES) { g_deg[i] = 0; g_cur[i] = 0; }
}
__global__ void k_hist(const int* __restrict__ dst) {
    int e = blockIdx.x * blockDim.x + threadIdx.x;
    if (e < N_EDGES) atomicAdd(&g_deg[__ldg(dst + e)], 1);
}
#define SCAN_T 1024
#define SCAN_CH 49
__global__ __launch_bounds__(SCAN_T)
void k_scan() {
    __shared__ int s[SCAN_T];
    int t = threadIdx.x;
    int start = t * SCAN_CH;
    int end = min(start + SCAN_CH, N_NODES);
    int sum = 0;
    for (int i = start; i < end; i++) sum += g_deg[i];
    s[t] = sum;
    __syncthreads();
    #pragma unroll
    for (int d = 1; d < SCAN_T; d <<= 1) {
        int x = (t >= d) ? s[t - d] : 0;
        __syncthreads();
        s[t] += x;
        __syncthreads();
    }
    int run = (t > 0) ? s[t - 1] : 0;
    for (int i = start; i < end; i++) { g_off[i] = run; run += g_deg[i]; }
}
__global__ void k_place(const int* __restrict__ src, const int* __restrict__ dst) {
    int e = blockIdx.x * blockDim.x + threadIdx.x;
    if (e >= N_EDGES) return;
    int d = __ldg(dst + e);
    int pos = g_off[d] + atomicAdd(&g_cur[d], 1);
    g_esrc[pos] = __ldg(src + e);
}

// ===========================================================================
// K_agg (round-13 winner, verbatim)
// ===========================================================================
__global__ void k_agg(const float4* __restrict__ x, int use_x) {
    if (blockIdx.x == 0 && threadIdx.x < 2 * DIM) g_stats[threadIdx.x] = 0.0f;
    int gt = blockIdx.x * blockDim.x + threadIdx.x;
    int node = gt >> 5;
    int lane = gt & 31;
    if (node >= N_NODES) return;
    const float4* hin = use_x ? x : (const float4*)g_h;

    float4 acc = __ldg(hin + node * 32 + lane);
    int e   = __ldg(g_off + node);
    int end = e + __ldg(g_deg + node);

    for (; e + 3 < end; e += 4) {
        int s0 = __ldg(g_esrc + e);
        int s1 = __ldg(g_esrc + e + 1);
        int s2 = __ldg(g_esrc + e + 2);
        int s3 = __ldg(g_esrc + e + 3);
        float4 v0 = __ldg(hin + s0 * 32 + lane);
        float4 v1 = __ldg(hin + s1 * 32 + lane);
        float4 v2 = __ldg(hin + s2 * 32 + lane);
        float4 v3 = __ldg(hin + s3 * 32 + lane);
        acc.x += v0.x + v1.x + v2.x + v3.x;
        acc.y += v0.y + v1.y + v2.y + v3.y;
        acc.z += v0.z + v1.z + v2.z + v3.z;
        acc.w += v0.w + v1.w + v2.w + v3.w;
    }
    for (; e < end; e++) {
        int s0 = __ldg(g_esrc + e);
        float4 v0 = __ldg(hin + s0 * 32 + lane);
        acc.x += v0.x; acc.y += v0.y; acc.z += v0.z; acc.w += v0.w;
    }
    ((float4*)g_agg)[node * 32 + lane] = acc;
}

// ===========================================================================
// K_mlp (mma.sync bf16 3-term split):
//   h2 = relu(relu(agg@W1+b1)@W2+b2) in-place on g_agg + BN stats.
//   8 warps; warp w = rows 16w..16w+15; 16 N-tiles of 8 cols each.
// ===========================================================================
__global__ __launch_bounds__(256, 1)
void k_mlp(const float* __restrict__ W1, const float* __restrict__ b1,
           const float* __restrict__ W2, const float* __restrict__ b2) {
    extern __shared__ char smc[];
    unsigned short* sAh = (unsigned short*)(smc + S_AH);
    unsigned short* sAl = (unsigned short*)(smc + S_AL);
    unsigned short* sW1h = (unsigned short*)(smc + S_W1H);
    unsigned short* sW1l = (unsigned short*)(smc + S_W1L);
    unsigned short* sW2h = (unsigned short*)(smc + S_W2H);
    unsigned short* sW2l = (unsigned short*)(smc + S_W2L);
    float* s_stats = (float*)(smc + S_STAT);

    const int tid  = threadIdx.x;
    const int base = blockIdx.x * MROWS;
    const int lane = tid & 31;
    const int w    = tid >> 5;
    const int g    = lane >> 2;
    const int tig  = lane & 3;
    const int r0   = w * 16;

    s_stats[tid] = 0.f;

    // ---- fill A (split hi/lo) ----
    const float4* A4 = (const float4*)g_agg;
    #pragma unroll
    for (int i = 0; i < 16; i++) {
        int idx = tid + i * 256;           // 0..4095
        int r = idx >> 5, kq = idx & 31;
        float4 v = make_float4(0.f, 0.f, 0.f, 0.f);
        if (base + r < N_NODES) v = __ldg(A4 + (size_t)(base + r) * 32 + kq);
        unsigned short hx, lx, hy, ly, hz, lz, hw, lw;
        bsplit(v.x, hx, lx); bsplit(v.y, hy, ly);
        bsplit(v.z, hz, lz); bsplit(v.w, hw, lw);
        uint32_t* ph = (uint32_t*)sAh + r * WST + kq * 2;
        uint32_t* pl = (uint32_t*)sAl + r * WST + kq * 2;
        ph[0] = pk(hx, hy); ph[1] = pk(hz, hw);
        pl[0] = pk(lx, ly); pl[1] = pk(lz, lw);
    }
    // ---- fill W1 and W2 transposed [n][k] (split hi/lo) ----
    #pragma unroll
    for (int i = 0; i < 64; i++) {
        int idx = tid + i * 256;           // 0..16383
        int k = idx >> 7, n = idx & 127;   // W[k][n]
        unsigned short h, l;
        bsplit(__ldg(W1 + idx), h, l);
        sW1h[n * HST + k] = h; sW1l[n * HST + k] = l;
        bsplit(__ldg(W2 + idx), h, l);
        sW2h[n * HST + k] = h; sW2l[n * HST + k] = l;
    }
    __syncthreads();

    float d[16][4];
    #pragma unroll
    for (int nt = 0; nt < 16; nt++)
        #pragma unroll
        for (int j = 0; j < 4; j++) d[nt][j] = 0.f;

    // =============== GEMM 1: A @ W1 ===============
    {
        const uint32_t* wAh = (const uint32_t*)sAh;
        const uint32_t* wAl = (const uint32_t*)sAl;
        const uint32_t* wBh = (const uint32_t*)sW1h;
        const uint32_t* wBl = (const uint32_t*)sW1l;
        #pragma unroll
        for (int ks = 0; ks < 8; ks++) {
            uint32_t ah[4], al[4];
            int abase = (r0 + g) * WST + ks * 8 + tig;
            ah[0] = wAh[abase];                 al[0] = wAl[abase];
            ah[1] = wAh[abase + 8 * WST];       al[1] = wAl[abase + 8 * WST];
            ah[2] = wAh[abase + 4];             al[2] = wAl[abase + 4];
            ah[3] = wAh[abase + 8 * WST + 4];   al[3] = wAl[abase + 8 * WST + 4];
            #pragma unroll
            for (int nt = 0; nt < 16; nt++) {
                int bbase = (nt * 8 + g) * WST + ks * 8 + tig;
                uint32_t bh0 = wBh[bbase], bh1 = wBh[bbase + 4];
                uint32_t bl0 = wBl[bbase], bl1 = wBl[bbase + 4];
                mma16816(d[nt], ah, bh0, bh1);
                mma16816(d[nt], ah, bl0, bl1);
                mma16816(d[nt], al, bh0, bh1);
            }
        }
    }
    __syncthreads();   // everyone done reading A before H1 overwrites it

    // ---- epilogue 1: relu(+b1) -> split back into A smem buffers ----
    #pragma unroll
    for (int nt = 0; nt < 16; nt++) {
        int c = nt * 8 + 2 * tig;
        float bb0 = __ldg(b1 + c), bb1 = __ldg(b1 + c + 1);
        float f0 = fmaxf(d[nt][0] + bb0, 0.f);
        float f1 = fmaxf(d[nt][1] + bb1, 0.f);
        float f2 = fmaxf(d[nt][2] + bb0, 0.f);
        float f3 = fmaxf(d[nt][3] + bb1, 0.f);
        unsigned short h0, l0, h1, l1;
        int wi0 = (r0 + g) * WST + nt * 4 + tig;
        int wi1 = (r0 + g + 8) * WST + nt * 4 + tig;
        bsplit(f0, h0, l0); bsplit(f1, h1, l1);
        ((uint32_t*)sAh)[wi0] = pk(h0, h1);
        ((uint32_t*)sAl)[wi0] = pk(l0, l1);
        bsplit(f2, h0, l0); bsplit(f3, h1, l1);
        ((uint32_t*)sAh)[wi1] = pk(h0, h1);
        ((uint32_t*)sAl)[wi1] = pk(l0, l1);
        d[nt][0] = d[nt][1] = d[nt][2] = d[nt][3] = 0.f;
    }
    __syncthreads();

    // =============== GEMM 2: H1 @ W2 ===============
    {
        const uint32_t* wAh = (const uint32_t*)sAh;
        const uint32_t* wAl = (const uint32_t*)sAl;
        const uint32_t* wBh = (const uint32_t*)sW2h;
        const uint32_t* wBl = (const uint32_t*)sW2l;
        #pragma unroll
        for (int ks = 0; ks < 8; ks++) {
            uint32_t ah[4], al[4];
            int abase = (r0 + g) * WST + ks * 8 + tig;
            ah[0] = wAh[abase];                 al[0] = wAl[abase];
            ah[1] = wAh[abase + 8 * WST];       al[1] = wAl[abase + 8 * WST];
            ah[2] = wAh[abase + 4];             al[2] = wAl[abase + 4];
            ah[3] = wAh[abase + 8 * WST + 4];   al[3] = wAl[abase + 8 * WST + 4];
            #pragma unroll
            for (int nt = 0; nt < 16; nt++) {
                int bbase = (nt * 8 + g) * WST + ks * 8 + tig;
                uint32_t bh0 = wBh[bbase], bh1 = wBh[bbase + 4];
                uint32_t bl0 = wBl[bbase], bl1 = wBl[bbase + 4];
                mma16816(d[nt], ah, bh0, bh1);
                mma16816(d[nt], ah, bl0, bl1);
                mma16816(d[nt], al, bh0, bh1);
            }
        }
    }

    // ---- epilogue 2: relu(+b2) -> g_agg (in place), BN stats ----
    const int rowA = base + r0 + g;
    const int rowB = rowA + 8;
    const bool vA = (rowA < N_NODES);
    const bool vB = (rowB < N_NODES);
    #pragma unroll
    for (int nt = 0; nt < 16; nt++) {
        int c = nt * 8 + 2 * tig;
        float bb0 = __ldg(b2 + c), bb1 = __ldg(b2 + c + 1);
        float v0 = fmaxf(d[nt][0] + bb0, 0.f);
        float v1 = fmaxf(d[nt][1] + bb1, 0.f);
        float v2 = fmaxf(d[nt][2] + bb0, 0.f);
        float v3 = fmaxf(d[nt][3] + bb1, 0.f);
        if (vA) *(float2*)(g_agg + (size_t)rowA * DIM + c) = make_float2(v0, v1);
        if (vB) *(float2*)(g_agg + (size_t)rowB * DIM + c) = make_float2(v2, v3);

        float s0 = (vA ? v0 : 0.f) + (vB ? v2 : 0.f);
        float s1 = (vA ? v1 : 0.f) + (vB ? v3 : 0.f);
        float q0 = (vA ? v0 * v0 : 0.f) + (vB ? v2 * v2 : 0.f);
        float q1 = (vA ? v1 * v1 : 0.f) + (vB ? v3 * v3 : 0.f);
        #pragma unroll
        for (int off = 4; off < 32; off <<= 1) {
            s0 += __shfl_xor_sync(0xFFFFFFFFu, s0, off);
            s1 += __shfl_xor_sync(0xFFFFFFFFu, s1, off);
            q0 += __shfl_xor_sync(0xFFFFFFFFu, q0, off);
            q1 += __shfl_xor_sync(0xFFFFFFFFu, q1, off);
        }
        if (lane < 4) {
            atomicAdd(&s_stats[c], s0);
            atomicAdd(&s_stats[c + 1], s1);
            atomicAdd(&s_stats[DIM + c], q0);
            atomicAdd(&s_stats[DIM + c + 1], q1);
        }
    }
    __syncthreads();
    atomicAdd(&g_stats[tid], s_stats[tid]);
}

// ===========================================================================
// K_apply (round-13 winner, verbatim): BN -> g_h, pool into out
// ===========================================================================
__global__ void k_apply(const int* __restrict__ batch, float* __restrict__ out,
                        const float* __restrict__ gamma, const float* __restrict__ beta,
                        int layer) {
    __shared__ float s_st[2 * DIM];
    if (threadIdx.x < DIM) {
        int f = threadIdx.x;
        float n = (float)N_NODES;
        float mean = g_stats[f] / n;
        float var = g_stats[DIM + f] / n - mean * mean;
        var = fmaxf(var, 0.f);
        float sc = rsqrtf(var + BN_EPS) * __ldg(gamma + f);
        s_st[f] = sc;
        s_st[DIM + f] = fmaf(-mean, sc, __ldg(beta + f));
    }
    __syncthreads();

    int idx = blockIdx.x * blockDim.x + threadIdx.x;  // 1.6M exact
    int row = idx >> 5, cq = idx & 31;
    float4 xv = ((const float4*)g_agg)[idx];
    float4 s = ((const float4*)s_st)[cq];
    float4 t = ((const float4*)s_st)[32 + cq];
    float4 y;
    y.x = fmaf(xv.x, s.x, t.x);
    y.y = fmaf(xv.y, s.y, t.y);
    y.z = fmaf(xv.z, s.z, t.z);
    y.w = fmaf(xv.w, s.w, t.w);
    ((float4*)g_h)[idx] = y;
    int g = __ldg(batch + row);
    red_add_v4((float4*)(out + g * (N_LAYERS * DIM) + layer * DIM + (cq << 2)), y);
}

// ---------------------------------------------------------------------------
extern "C" void kernel_launch(void* const* d_in, const int* in_sizes, int n_in,
                              void* d_out, int out_size) {
    const float* x      = (const float*)d_in[0];
    const int*   ei     = (const int*)d_in[1];
    const int*   batch  = (const int*)d_in[2];
    const float* W1s    = (const float*)d_in[3];
    const float* b1s    = (const float*)d_in[4];
    const float* W2s    = (const float*)d_in[5];
    const float* b2s    = (const float*)d_in[6];
    const float* gammas = (const float*)d_in[7];
    const float* betas  = (const float*)d_in[8];
    float* out = (float*)d_out;

    cudaFuncSetAttribute(k_mlp, cudaFuncAttributeMaxDynamicSharedMemorySize, S_TOTAL);

    const int* src = ei;
    const int* dst = ei + N_EDGES;

    const int node_blocks = (N_NODES * 32) / 256;                 // 6250
    const int edge_blocks = (N_EDGES + 255) / 256;                // 2344
    const int prep_blocks = (OUT_ELEMS + 255) / 256;              // 768
    const int mlp_blocks  = (N_NODES + MROWS - 1) / MROWS;        // 391

    k_prep<<<prep_blocks, 256>>>(out);
    k_hist<<<edge_blocks, 256>>>(dst);
    k_scan<<<1, SCAN_T>>>();
    k_place<<<edge_blocks, 256>>>(src, dst);

    for (int l = 0; l < N_LAYERS; l++) {
        int use_x = (l == 0) ? 1 : 0;
        k_agg<<<node_blocks, 256>>>((const float4*)x, use_x);
        k_mlp<<<mlp_blocks, 256, S_TOTAL>>>(
            W1s + l * DIM * DIM, b1s + l * DIM,
            W2s + l * DIM * DIM, b2s + l * DIM);
        k_apply<<<node_blocks, 256>>>(batch, out, gammas + l * DIM, betas + l * DIM, l);
    }
}